// round 10
// baseline (speedup 1.0000x reference)
#include <cuda_runtime.h>
#include <cuda_bf16.h>

// Bilateral filter 5x5, sigma_xy = sigma_z = 1, zero padding.
// X: [NC, 512, 512] fp32 (NC = 12), out same shape.
//
// R9 -> R10: PIXEL-PAIR vectorization. Each thread computes 2 horizontally
// adjacent pixels held in the two lanes of f32x2 registers.
//  * taps for the pair are adjacent tile elements -> LDS.64 row segments
//    (3 per row); even-dx tap-pairs are free register pairs, odd-dx need
//    one 2-MOV mix. LDS/pixel 20 -> 7.5, tap packing MOVs mostly gone.
//  * c/b/E/W*E precompute once per pair (packed), center + final store pairwise
//    (STG.64).
// Warp-instr count per 64 px: ~215 vs R4's ~322 (-33%); MUFU becomes top
// pipe (~13.8us). Same 16-EX2 + 8-poly + exact-center math as R8/R9.

#define TX   32
#define TYW  8
#define PXW  2
#define BW   (TX*PXW)         // 64 output cols per block
#define HALO 2
#define SW   (BW + 2*HALO)    // 68
#define SH   (TYW + 2*HALO)   // 12

typedef unsigned long long ull;

__device__ __forceinline__ ull pack2(float a, float b) {
    ull r; asm("mov.b64 %0, {%1, %2};" : "=l"(r) : "f"(a), "f"(b)); return r;
}
__device__ __forceinline__ void unpack2(ull v, float& a, float& b) {
    asm("mov.b64 {%0, %1}, %2;" : "=f"(a), "=f"(b) : "l"(v));
}
__device__ __forceinline__ ull fma2(ull a, ull b, ull c) {
    ull d; asm("fma.rn.f32x2 %0, %1, %2, %3;" : "=l"(d) : "l"(a), "l"(b), "l"(c)); return d;
}
__device__ __forceinline__ ull add2(ull a, ull b) {
    ull d; asm("add.rn.f32x2 %0, %1, %2;" : "=l"(d) : "l"(a), "l"(b)); return d;
}
__device__ __forceinline__ ull mul2(ull a, ull b) {
    ull d; asm("mul.rn.f32x2 %0, %1, %2;" : "=l"(d) : "l"(a), "l"(b)); return d;
}
__device__ __forceinline__ float ex2f(float a) {
    float s; asm("ex2.approx.ftz.f32 %0, %1;" : "=f"(s) : "f"(a)); return s;
}
// (hi of a, lo of b) -> packed pair for odd-dx taps
__device__ __forceinline__ ull mixhl(ull a, ull b) {
    float a0, a1, b0, b1;
    unpack2(a, a0, a1); unpack2(b, b0, b1);
    return pack2(a1, b0);
}

// L = -0.5*log2(e)
#define LCONST  (-0.72134752044448170f)
#define NEG2L   (1.44269504088896340f)
// degree-3 Chebyshev approx of e^{-u/2} on [0,1]
#define PK0 (0.99999770f)
#define PK1 (-0.49942563f)
#define PK2 (0.12219345f)
#define PK3 (-0.01622403f)
// spatial weights e^{-d2/2}
#define W5C (0.08208499862f)
#define W8C (0.01831563889f)

__global__ __launch_bounds__(TX * TYW)
void bilateral_kernel(const float* __restrict__ X, float* __restrict__ out)
{
    __shared__ __align__(8) float tile[SH][SW];

    const int H = 512, W = 512;
    const int z = blockIdx.z;
    const float* __restrict__ img = X + (size_t)z * H * W;

    const int gx0 = blockIdx.x * BW - HALO;
    const int gy0 = blockIdx.y * TYW - HALO;

    // Cooperative halo load: 12*68 = 816 elements, 256 threads (4 iters).
    const int tid = threadIdx.y * TX + threadIdx.x;
    #pragma unroll
    for (int i = tid; i < SH * SW; i += TX * TYW) {
        const int sy = i / SW;
        const int sx = i - sy * SW;
        const int gx = gx0 + sx;
        const int gy = gy0 + sy;
        float v = 0.0f;
        if ((unsigned)gx < (unsigned)W && (unsigned)gy < (unsigned)H)
            v = img[gy * W + gx];
        tile[sy][sx] = v;
    }
    __syncthreads();

    const int tx   = threadIdx.x;
    const int tyr  = threadIdx.y;
    const int col0 = 2 * tx;             // tile col of window-left (dx=0)

    // center pair: tile cols col0+2, col0+3 (8B aligned)
    const ull c2 = *(const ull*)&tile[tyr + 2][col0 + 2];
    float c0, c1; unpack2(c2, c0, c1);

    const ull L2c = pack2(LCONST, LCONST);
    const ull b2  = mul2(c2, pack2(NEG2L, NEG2L));
    const ull cn2 = c2 ^ 0x8000000080000000ULL;   // packed negate (LOP)
    // E = e^{c^2/2}: EX2 taps are implicitly E-scaled (arg omits L*c^2);
    // poly/center get an explicit E prescale; E cancels in the divide.
    const ull E2v = pack2(ex2f((-LCONST) * (c0 * c0)),
                          ex2f((-LCONST) * (c1 * c1)));

    const ull LD1 = pack2(LCONST * 1.0f, LCONST * 1.0f);
    const ull LD2 = pack2(LCONST * 2.0f, LCONST * 2.0f);
    const ull LD4 = pack2(LCONST * 4.0f, LCONST * 4.0f);
    const ull LD5 = pack2(LCONST * 5.0f, LCONST * 5.0f);
    const ull K3  = pack2(PK3, PK3);
    const ull K2  = pack2(PK2, PK2);
    const ull K1  = pack2(PK1, PK1);
    const ull K0  = pack2(PK0, PK0);
    const ull WE5 = mul2(E2v, pack2(W5C, W5C));
    const ull WE8 = mul2(E2v, pack2(W8C, W8C));

    // center tap (s_true = 1 -> E-scaled contribution E)
    ull num2 = mul2(E2v, c2);
    ull den2 = E2v;

    #define EX2TAP(P2, LDC)                                       \
    {                                                             \
        const ull t2 = fma2(L2c, P2, b2);                         \
        const ull a2 = fma2(P2, t2, LDC);                         \
        float a0, a1; unpack2(a2, a0, a1);                        \
        const ull s2 = pack2(ex2f(a0), ex2f(a1));                 \
        num2 = fma2(s2, P2, num2);                                \
        den2 = add2(den2, s2);                                    \
    }
    #define POLYTAP(P2, SC2)                                      \
    {                                                             \
        const ull dv = add2(P2, cn2);                             \
        const ull u2 = mul2(dv, dv);                              \
        ull s2 = fma2(u2, K3, K2);                                \
        s2 = fma2(u2, s2, K1);                                    \
        s2 = fma2(u2, s2, K0);                                    \
        s2 = mul2(s2, SC2);                                       \
        num2 = fma2(s2, P2, num2);                                \
        den2 = add2(den2, s2);                                    \
    }
    // load row rr as 3 aligned LDS.64 + 2 mixes -> 5 tap-pairs N{a..e}
    #define LOADROW(rr, N)                                        \
        const ull N##a = *(const ull*)&tile[rr][col0];            \
        const ull N##c = *(const ull*)&tile[rr][col0 + 2];        \
        const ull N##e = *(const ull*)&tile[rr][col0 + 4];        \
        const ull N##b = mixhl(N##a, N##c);                       \
        const ull N##d = mixhl(N##c, N##e);

    // dy = 0:  d2 = 8,5,4,5,8
    { LOADROW(tyr + 0, r0)
      POLYTAP(r0a, WE8) POLYTAP(r0b, WE5) EX2TAP(r0c, LD4)
      POLYTAP(r0d, WE5) POLYTAP(r0e, WE8) }
    // dy = 1:  d2 = 5,2,1,2,5
    { LOADROW(tyr + 1, r1)
      EX2TAP(r1a, LD5) EX2TAP(r1b, LD2) EX2TAP(r1c, LD1)
      EX2TAP(r1d, LD2) EX2TAP(r1e, LD5) }
    // dy = 2:  d2 = 4,1,(0),1,4  — center pair already loaded as c2
    { const ull r2a = *(const ull*)&tile[tyr + 2][col0];
      const ull r2e = *(const ull*)&tile[tyr + 2][col0 + 4];
      const ull r2b = mixhl(r2a, c2);
      const ull r2d = mixhl(c2, r2e);
      EX2TAP(r2a, LD4) EX2TAP(r2b, LD1) EX2TAP(r2d, LD1) EX2TAP(r2e, LD4) }
    // dy = 3:  d2 = 5,2,1,2,5
    { LOADROW(tyr + 3, r3)
      EX2TAP(r3a, LD5) EX2TAP(r3b, LD2) EX2TAP(r3c, LD1)
      EX2TAP(r3d, LD2) EX2TAP(r3e, LD5) }
    // dy = 4:  d2 = 8,5,4,5,8
    { LOADROW(tyr + 4, r4)
      POLYTAP(r4a, WE8) POLYTAP(r4b, WE5) EX2TAP(r4c, LD4)
      POLYTAP(r4d, WE5) POLYTAP(r4e, WE8) }

    #undef EX2TAP
    #undef POLYTAP
    #undef LOADROW

    float n0, n1, d0, d1;
    unpack2(num2, n0, n1);
    unpack2(den2, d0, d1);
    float2 res;
    res.x = __fdividef(n0, d0);
    res.y = __fdividef(n1, d1);

    const int gx = blockIdx.x * BW + col0;
    const int gy = blockIdx.y * TYW + tyr;
    *(float2*)&out[(size_t)z * H * W + gy * W + gx] = res;
}

extern "C" void kernel_launch(void* const* d_in, const int* in_sizes, int n_in,
                              void* d_out, int out_size)
{
    const float* X = (const float*)d_in[0];
    float* out = (float*)d_out;

    const int H = 512, W = 512;
    const int NC = in_sizes[0] / (H * W);   // 12 for (4,3,512,512)

    dim3 block(TX, TYW);
    dim3 grid(W / BW, H / TYW, NC);
    bilateral_kernel<<<grid, block>>>(X, out);
}